// round 1
// baseline (speedup 1.0000x reference)
#include <cuda_runtime.h>

// Problem shapes (fixed by the reference):
//   x  [B=256, T=100, I=512]   fp32
//   W1 [H=1024, I=512]         fp32
//   b1 [H]                     fp32
//   W2 [C=8, H=1024]           fp32
//   b2 [C]                     fp32
//   out[B=256, C=8]            fp32
#define T_STEPS 100
#define B_SZ    256
#define IN_F    512
#define HID     1024
#define CLS     8

// Scratch for cur = x @ W1^T + b1, laid out [b][t][h] (row m = b*T + t).
// 256*100*1024 floats = 104.86 MB — static device global (no allocations).
__device__ float g_cur[(size_t)B_SZ * T_STEPS * HID];

// ---------------------------------------------------------------------------
// Kernel 1: fp32 SGEMM  C[m][n] = sum_k A[m][k] * W[n][k] + bias[n]
//   A = x viewed as [M=25600, K=512] (row m = b*T+t), W = W1 [N=1024, K=512].
//   Tiling: 128x128 block tile, BK=16, 256 threads, 8x8 microtile/thread.
// ---------------------------------------------------------------------------
__global__ __launch_bounds__(256, 2)
void gemm_fc1(const float* __restrict__ A, const float* __restrict__ W,
              const float* __restrict__ bias) {
    // Padded to 132 floats/row: keeps float4 LDS alignment (132%4==0) and
    // reduces transpose-store bank conflicts.
    __shared__ float As[16][132];
    __shared__ float Bs[16][132];

    const int tid = threadIdx.x;
    const int tx  = tid & 15;    // micro-tile column group (n)
    const int ty  = tid >> 4;    // micro-tile row group (m)

    const float* Ab = A + (size_t)blockIdx.y * 128 * IN_F;
    const float* Wb = W + (size_t)blockIdx.x * 128 * IN_F;

    // Cooperative load mapping: 4 threads per row, each loads one float4.
    const int lrow = tid >> 2;          // 0..63 (two passes cover 128 rows)
    const int lk   = (tid & 3) << 2;    // 0,4,8,12

    float acc[8][8];
    #pragma unroll
    for (int i = 0; i < 8; i++)
        #pragma unroll
        for (int j = 0; j < 8; j++) acc[i][j] = 0.0f;

    for (int k0 = 0; k0 < IN_F; k0 += 16) {
        #pragma unroll
        for (int r = 0; r < 2; r++) {
            const int row = lrow + r * 64;
            const float4 va = *(const float4*)(Ab + (size_t)row * IN_F + k0 + lk);
            As[lk + 0][row] = va.x;
            As[lk + 1][row] = va.y;
            As[lk + 2][row] = va.z;
            As[lk + 3][row] = va.w;
            const float4 vb = *(const float4*)(Wb + (size_t)row * IN_F + k0 + lk);
            Bs[lk + 0][row] = vb.x;
            Bs[lk + 1][row] = vb.y;
            Bs[lk + 2][row] = vb.z;
            Bs[lk + 3][row] = vb.w;
        }
        __syncthreads();

        #pragma unroll
        for (int k = 0; k < 16; k++) {
            float a[8], b[8];
            *(float4*)(a)     = *(const float4*)(&As[k][ty * 8]);
            *(float4*)(a + 4) = *(const float4*)(&As[k][ty * 8 + 4]);
            *(float4*)(b)     = *(const float4*)(&Bs[k][tx * 8]);
            *(float4*)(b + 4) = *(const float4*)(&Bs[k][tx * 8 + 4]);
            #pragma unroll
            for (int i = 0; i < 8; i++)
                #pragma unroll
                for (int j = 0; j < 8; j++)
                    acc[i][j] = fmaf(a[i], b[j], acc[i][j]);
        }
        __syncthreads();
    }

    // Epilogue: add bias, store two float4 per row.
    float bv[8];
    #pragma unroll
    for (int j = 0; j < 8; j++) bv[j] = bias[blockIdx.x * 128 + tx * 8 + j];

    #pragma unroll
    for (int i = 0; i < 8; i++) {
        const size_t m = (size_t)blockIdx.y * 128 + ty * 8 + i;
        float* dst = g_cur + m * HID + blockIdx.x * 128 + tx * 8;
        float4 o0 = make_float4(acc[i][0] + bv[0], acc[i][1] + bv[1],
                                acc[i][2] + bv[2], acc[i][3] + bv[3]);
        float4 o1 = make_float4(acc[i][4] + bv[4], acc[i][5] + bv[5],
                                acc[i][6] + bv[6], acc[i][7] + bv[7]);
        *(float4*)(dst)     = o0;
        *(float4*)(dst + 4) = o1;
    }
}

// ---------------------------------------------------------------------------
// Kernel 2: LIF scan over T per (b,h), fused with the [B,H]x[H,C] output GEMM.
//   One block per batch element b, 1024 threads (one per hidden unit h).
//   snntorch Leaky, reset='subtract', threshold=1:
//     reset   = (mem > 1)
//     mem     = 0.9*mem + cur[t] - reset
//     spk_sum += (mem > 1)
//   logits[b][c] = sum_h spk_sum[h]*W2[c][h] + 100*b2[c]
// ---------------------------------------------------------------------------
__global__ __launch_bounds__(1024, 1)
void lif_reduce(const float* __restrict__ W2, const float* __restrict__ b2,
                float* __restrict__ out) {
    const int b = blockIdx.x;
    const int h = threadIdx.x;
    const float* p = g_cur + (size_t)b * T_STEPS * HID + h;

    float mem = 0.0f, spk_sum = 0.0f;
    #pragma unroll 4
    for (int t = 0; t < T_STEPS; t++) {
        const float c = p[t * HID];
        const float reset = (mem > 1.0f) ? 1.0f : 0.0f;
        mem = 0.9f * mem + c - reset;
        spk_sum += (mem > 1.0f) ? 1.0f : 0.0f;
    }

    // Per-thread partial logits
    float part[8];
    #pragma unroll
    for (int c = 0; c < 8; c++) part[c] = spk_sum * W2[c * HID + h];

    // Warp reduction of each of the 8 partials
    #pragma unroll
    for (int c = 0; c < 8; c++)
        #pragma unroll
        for (int o = 16; o > 0; o >>= 1)
            part[c] += __shfl_down_sync(0xffffffffu, part[c], o);

    __shared__ float s_red[8][32];
    const int lane = h & 31, warp = h >> 5;
    if (lane == 0) {
        #pragma unroll
        for (int c = 0; c < 8; c++) s_red[c][warp] = part[c];
    }
    __syncthreads();

    // 8 warps (tid < 256): warp w reduces the 32 partials for class c = w
    if (threadIdx.x < 256) {
        const int c = threadIdx.x >> 5;
        const int w = threadIdx.x & 31;
        float v = s_red[c][w];
        #pragma unroll
        for (int o = 16; o > 0; o >>= 1)
            v += __shfl_down_sync(0xffffffffu, v, o);
        if (w == 0) out[b * CLS + c] = v + 100.0f * b2[c];
    }
}

// ---------------------------------------------------------------------------
extern "C" void kernel_launch(void* const* d_in, const int* in_sizes, int n_in,
                              void* d_out, int out_size) {
    const float* x  = (const float*)d_in[0];  // [256,100,512]
    const float* W1 = (const float*)d_in[1];  // [1024,512]
    const float* b1 = (const float*)d_in[2];  // [1024]
    const float* W2 = (const float*)d_in[3];  // [8,1024]
    const float* b2 = (const float*)d_in[4];  // [8]
    float* out = (float*)d_out;               // [256,8]

    // GEMM: M = 25600 rows (b*T+t), tiled 128 -> grid.y = 200; N = 1024 -> grid.x = 8
    dim3 ggrid(HID / 128, (B_SZ * T_STEPS) / 128);
    gemm_fc1<<<ggrid, 256>>>(x, W1, b1);

    // LIF + output reduction: one block per batch element
    lif_reduce<<<B_SZ, 1024>>>(W2, b2, out);
}